// round 17
// baseline (speedup 1.0000x reference)
#include <cuda_runtime.h>
#include <cuda_fp16.h>
#include <cstdint>

// Problem: B=2, S=2048, D=1024, H=16, DK=64.  Output [2,2048,1024] f32.
// Harness PTX target is compute_100 (no 'a') — tcgen05 unavailable.
// All operands 1-term fp16 (precision ledger closed, ~6.8e-4 of 1e-3).
// R17: GEMM BK=32 stages — one barrier per 32-k, all fragments (both
// k-halves) loaded before 32 mma so ldsm latency overlaps tensor work.

#define BATCH 2
#define SEQ   2048
#define DMODEL 1024
#define NHEAD 16
#define HDIM  64

// all-fp16 hi-only buffers
__device__ __half g_Xh [BATCH * SEQ * DMODEL];
__device__ __half g_Wqh[DMODEL * DMODEL];
__device__ __half g_Wkh[DMODEL * DMODEL];
__device__ __half g_Wvh[DMODEL * DMODEL];
__device__ __half g_Woh[DMODEL * DMODEL];
__device__ __half g_Qh [BATCH * SEQ * DMODEL];
__device__ __half g_Kh [BATCH * SEQ * DMODEL];
__device__ __half g_Vh [BATCH * SEQ * DMODEL];
__device__ __half g_AOh[BATCH * SEQ * DMODEL];

// Q pre-scale: (1/sqrt(64)) * log2(e)
#define QSCALE 0.18033688011112043f

// ---------------------------------------------------------------------------
__device__ __forceinline__ uint32_t pack_f16(float a, float b) {
    __half ha = __float2half_rn(a), hb = __float2half_rn(b);
    return (uint32_t)__half_as_ushort(ha) | ((uint32_t)__half_as_ushort(hb) << 16);
}
__device__ __forceinline__ uint32_t cvta_smem(const void* p) {
    return (uint32_t)__cvta_generic_to_shared(p);
}
__device__ __forceinline__ void cp_async16(uint32_t dst, const void* src) {
    asm volatile("cp.async.cg.shared.global [%0], [%1], 16;" :: "r"(dst), "l"(src));
}
__device__ __forceinline__ void cp_commit() {
    asm volatile("cp.async.commit_group;");
}
__device__ __forceinline__ void ldsm4(uint32_t (&r)[4], uint32_t addr) {
    asm volatile("ldmatrix.sync.aligned.m8n8.x4.shared.b16 {%0,%1,%2,%3}, [%4];"
                 : "=r"(r[0]), "=r"(r[1]), "=r"(r[2]), "=r"(r[3]) : "r"(addr));
}
__device__ __forceinline__ void ldsm4t(uint32_t (&r)[4], uint32_t addr) {
    asm volatile("ldmatrix.sync.aligned.m8n8.x4.trans.shared.b16 {%0,%1,%2,%3}, [%4];"
                 : "=r"(r[0]), "=r"(r[1]), "=r"(r[2]), "=r"(r[3]) : "r"(addr));
}
__device__ __forceinline__ void mma16816(float (&d)[4], const uint32_t (&a)[4],
                                         uint32_t b0, uint32_t b1) {
    asm volatile(
        "mma.sync.aligned.m16n8k16.row.col.f32.f16.f16.f32 "
        "{%0,%1,%2,%3}, {%4,%5,%6,%7}, {%8,%9}, {%0,%1,%2,%3};\n"
        : "+f"(d[0]), "+f"(d[1]), "+f"(d[2]), "+f"(d[3])
        : "r"(a[0]), "r"(a[1]), "r"(a[2]), "r"(a[3]), "r"(b0), "r"(b1));
}
__device__ __forceinline__ float ex2(float x) {
    float y;
    asm("ex2.approx.ftz.f32 %0, %1;" : "=f"(y) : "f"(x));
    return y;
}
__device__ __forceinline__ uint32_t h2exp2_pack(float a, float b, float& fa, float& fb) {
    __half2 h = __floats2half2_rn(a, b);
    __half2 e = h2exp2(h);
    float2 f = __half22float2(e);
    fa = f.x; fb = f.y;
    return *(uint32_t*)&e;
}

// ---------------------------------------------------------------------------
// Fused prep: z = 0..3 -> X chunks, 4..7 -> Wq/Wk/Wv/Wo.
// ---------------------------------------------------------------------------
__global__ __launch_bounds__(256) void conv_all(const float* __restrict__ X,
                                                const float* __restrict__ w0,
                                                const float* __restrict__ w1,
                                                const float* __restrict__ w2,
                                                const float* __restrict__ w3,
                                                __half* __restrict__ Xh,
                                                __half* __restrict__ d0,
                                                __half* __restrict__ d1,
                                                __half* __restrict__ d2,
                                                __half* __restrict__ d3, int n4)
{
    int i = blockIdx.x * blockDim.x + threadIdx.x;
    if (i >= n4) return;
    const int z = blockIdx.y;
    const float4* src;
    uint2* dst;
    if (z < 4) {
        src = ((const float4*)X) + (size_t)z * n4;
        dst = ((uint2*)Xh) + (size_t)z * n4;
    } else {
        const float* w = (z == 4) ? w0 : (z == 5) ? w1 : (z == 6) ? w2 : w3;
        __half* d = (z == 4) ? d0 : (z == 5) ? d1 : (z == 6) ? d2 : d3;
        src = (const float4*)w;
        dst = (uint2*)d;
    }
    float4 v = src[i];
    dst[i] = make_uint2(pack_f16(v.x, v.y), pack_f16(v.z, v.w));
}

// ===========================================================================
// 1-term fp16 GEMM core, BK=32: C = Ah @ Bh.  128x128 tile, 256 thr,
// 8 warps (2m x 4n), 4-stage cp.async ring, ONE sync per 32-k.
// A region 128 rows x 80 B (64 data + 16 pad, stride 5 banks, coprime 8);
// B region 32 rows x 272 B.  Stage 18944 B, 4 stages = 75776 B.
// MODE 0: fp32 C out.  MODE 2: fp16 out, scaled.
// ===========================================================================
#define G2_AH  0
#define G2_BH  10240
#define G2_STG 18944
#define G2_SMEM (4 * G2_STG)   // 75776 B

template<int MODE>
__device__ __forceinline__ void gemm_core(const __half* __restrict__ Ah,
                                          const __half* __restrict__ Bh,
                                          float* __restrict__ C,
                                          __half* __restrict__ Chi,
                                          float scale, int M, int N, int K)
{
    extern __shared__ char Gs[];
    const uint32_t smb = cvta_smem(Gs);

    const int tid  = threadIdx.x;
    const int warp = tid >> 5;
    const int lane = tid & 31;
    const int g    = lane >> 2;
    const int tig  = lane & 3;

    const int wm = (warp & 1) * 64;
    const int wn = (warp >> 1) * 32;

    const int bx = blockIdx.x;
    const int by = blockIdx.y;

    // fill assignments (conflict-free store phases)
    const int a_row = tid & 127;
    const int a_cb  = (tid >> 7) * 2;    // chunk base 0 or 2 (of 4)
    const int b_row = tid & 31;
    const int b_cb  = (tid >> 5) * 2;    // chunk base 0,2,...,14 (of 16)

    const __half* ag = Ah + (size_t)(by * 128 + a_row) * K + a_cb * 8;
    const __half* bg = Bh + (size_t)b_row * N + bx * 128 + b_cb * 8;

    const uint32_t a_dst = a_row * 80 + a_cb * 16;
    const uint32_t b_dst = b_row * 272 + b_cb * 16;

    const int niter = K >> 5;   // 32

#define G_FILL(stg, kb)                                                        \
    do {                                                                       \
        uint32_t s = smb + (stg) * G2_STG;                                     \
        size_t ko = (size_t)(kb) * 32;                                         \
        cp_async16(s + G2_AH + a_dst,      ag + ko);                           \
        cp_async16(s + G2_AH + a_dst + 16, ag + ko + 8);                       \
        cp_async16(s + G2_BH + b_dst,      bg + ko * N);                       \
        cp_async16(s + G2_BH + b_dst + 16, bg + ko * N + 8);                   \
    } while (0)

    G_FILL(0, 0); cp_commit();
    G_FILL(1, 1); cp_commit();

    const uint32_t arel = (uint32_t)((wm + (lane & 15)) * 80 + ((lane >> 4) << 4));
    const uint32_t brel = (uint32_t)((((lane & 7) + (((lane >> 3) & 1) << 3)) * 272) +
                                     wn * 2 + ((lane >> 4) << 4));

    float acc[4][4][4];
#pragma unroll
    for (int i = 0; i < 4; i++)
#pragma unroll
        for (int j = 0; j < 4; j++)
#pragma unroll
            for (int e = 0; e < 4; e++) acc[i][j][e] = 0.0f;

    for (int it = 0; it < niter; it++) {
        if (it + 2 < niter) {
            G_FILL((it + 2) & 3, it + 2);
            cp_commit();
            asm volatile("cp.async.wait_group 2;");
        } else if (it + 1 < niter) {
            asm volatile("cp.async.wait_group 1;");
        } else {
            asm volatile("cp.async.wait_group 0;");
        }
        __syncthreads();

        const uint32_t sb = smb + (it & 3) * G2_STG;

        // load ALL fragments for both k-halves, then 32 mma (latency overlap)
        uint32_t a0[4][4], a1[4][4], b0[2][4], b1[2][4];
#pragma unroll
        for (int mf = 0; mf < 4; mf++)
            ldsm4(a0[mf], sb + G2_AH + arel + mf * 16 * 80);
#pragma unroll
        for (int dg = 0; dg < 2; dg++)
            ldsm4t(b0[dg], sb + G2_BH + brel + dg * 32);
#pragma unroll
        for (int mf = 0; mf < 4; mf++)
            ldsm4(a1[mf], sb + G2_AH + arel + 32 + mf * 16 * 80);
#pragma unroll
        for (int dg = 0; dg < 2; dg++)
            ldsm4t(b1[dg], sb + G2_BH + brel + 4352 + dg * 32);

#pragma unroll
        for (int dg = 0; dg < 2; dg++)
#pragma unroll
            for (int mf = 0; mf < 4; mf++) {
                mma16816(acc[mf][2 * dg],     a0[mf], b0[dg][0], b0[dg][1]);
                mma16816(acc[mf][2 * dg + 1], a0[mf], b0[dg][2], b0[dg][3]);
            }
#pragma unroll
        for (int dg = 0; dg < 2; dg++)
#pragma unroll
            for (int mf = 0; mf < 4; mf++) {
                mma16816(acc[mf][2 * dg],     a1[mf], b1[dg][0], b1[dg][1]);
                mma16816(acc[mf][2 * dg + 1], a1[mf], b1[dg][2], b1[dg][3]);
            }
    }
#undef G_FILL

#pragma unroll
    for (int mf = 0; mf < 4; mf++) {
#pragma unroll
        for (int nf = 0; nf < 4; nf++) {
            int row = by * 128 + wm + mf * 16 + g;
            int col = bx * 128 + wn + nf * 8 + 2 * tig;
            if (MODE == 0) {
                *(float2*)(C + (size_t)row * N + col) =
                    make_float2(acc[mf][nf][0], acc[mf][nf][1]);
                *(float2*)(C + (size_t)(row + 8) * N + col) =
                    make_float2(acc[mf][nf][2], acc[mf][nf][3]);
            } else {
                *(uint32_t*)(Chi + (size_t)row * N + col) =
                    pack_f16(acc[mf][nf][0] * scale, acc[mf][nf][1] * scale);
                *(uint32_t*)(Chi + (size_t)(row + 8) * N + col) =
                    pack_f16(acc[mf][nf][2] * scale, acc[mf][nf][3] * scale);
            }
        }
    }
}

// Fused QKV: gridDim.z = 3 selects weight/output/scale.
__global__ __launch_bounds__(256, 2) void gemm_qkv(const __half* __restrict__ Xh,
                                                   const __half* __restrict__ Wq,
                                                   const __half* __restrict__ Wk,
                                                   const __half* __restrict__ Wv,
                                                   __half* __restrict__ Qo,
                                                   __half* __restrict__ Ko,
                                                   __half* __restrict__ Vo,
                                                   int M, int N, int K)
{
    const int z = blockIdx.z;
    const __half* W = (z == 0) ? Wq : (z == 1) ? Wk : Wv;
    __half* O = (z == 0) ? Qo : (z == 1) ? Ko : Vo;
    const float sc = (z == 0) ? QSCALE : 1.0f;
    gemm_core<2>(Xh, W, nullptr, O, sc, M, N, K);
}

__global__ __launch_bounds__(256, 2) void gemm_out(const __half* __restrict__ Ah,
                                                   const __half* __restrict__ Wo,
                                                   float* __restrict__ C,
                                                   int M, int N, int K)
{
    gemm_core<0>(Ah, Wo, C, nullptr, 1.0f, M, N, K);
}

// ===========================================================================
// Flash attention (unchanged from R16): pure fp16 operands, h2exp2 packed
// softmax, 4-stage cp.async KV ring, ONE sync per kv-block.
// CTA = 128 q-rows x (b,h), 8 warps x m16n64, BKV=64.  Smem 92160 B.
// ===========================================================================
#define BQ 128
#define BKV 64
#define FSTR  72
#define FSTRB (FSTR * 2)

#define OFF_QH 0
#define OFF_KV0 (BQ * FSTRB)              // 18432
#define KVBUF  (BKV * FSTRB)              // 9216
#define VH_REL KVBUF
#define KVSTAGE (2 * KVBUF)               // 18432
#define FLASH_SMEM (OFF_KV0 + 4 * KVSTAGE)  // 92160

__global__ __launch_bounds__(256, 2) void flash_mma(const __half* __restrict__ Qh,
                                                    const __half* __restrict__ Kh,
                                                    const __half* __restrict__ Vh,
                                                    __half* __restrict__ Oh)
{
    extern __shared__ char Sm[];
    const uint32_t smb = cvta_smem(Sm);

    const int qb = gridDim.x - 1 - blockIdx.x;
    const int h  = blockIdx.y;
    const int b  = blockIdx.z;

    const int tid  = threadIdx.x;
    const int w    = tid >> 5;
    const int lane = tid & 31;
    const int g    = lane >> 2;
    const int tig  = lane & 3;
    const int mrow = w * 16;

    const size_t base = ((size_t)b * SEQ) * DMODEL + (size_t)h * HDIM;
    const int nkv = 2 * qb + 2;

    const int kvrow = tid >> 2;
    const int kvc0  = (tid & 3) * 2;

#define F_FILL(stg, blk)                                                       \
    do {                                                                       \
        const size_t roff = base + (size_t)((blk) * BKV + kvrow) * DMODEL;     \
        const uint32_t dr = smb + OFF_KV0 + (stg) * KVSTAGE + kvrow * FSTRB;   \
        _Pragma("unroll")                                                      \
        for (int j = 0; j < 2; j++) {                                          \
            int ch = kvc0 + j;                                                 \
            cp_async16(dr + ch * 16,          Kh + roff + ch * 8);             \
            cp_async16(dr + VH_REL + ch * 16, Vh + roff + ch * 8);             \
        }                                                                      \
    } while (0)

    {
        const int row = tid >> 1;
        const int cg0 = (tid & 1) * 4;
        const __half* qsh = Qh + base + (size_t)(qb * BQ + row) * DMODEL;
        const uint32_t dh = smb + OFF_QH + row * FSTRB;
#pragma unroll
        for (int j = 0; j < 4; j++) {
            int ch = cg0 + j;
            cp_async16(dh + ch * 16, qsh + ch * 8);
        }
    }
    F_FILL(0, 0); cp_commit();
    F_FILL(1, 1); cp_commit();

    const uint32_t qrel = (uint32_t)((mrow + (lane & 15)) * FSTRB + ((lane >> 4) << 4));
    const uint32_t krel = (uint32_t)((((lane & 7) + ((lane >> 4) << 3)) * FSTRB) +
                                     (((lane >> 3) & 1) << 4));
    const uint32_t vrel = (uint32_t)((((lane & 7) + (((lane >> 3) & 1) << 3)) * FSTRB) +
                                     ((lane >> 4) << 4));
    const uint32_t qaddr0 = smb + OFF_QH + qrel;

    float oacc[8][4];
#pragma unroll
    for (int nf = 0; nf < 8; nf++)
#pragma unroll
        for (int e = 0; e < 4; e++) oacc[nf][e] = 0.0f;
    float m0 = -1e30f, m1 = -1e30f, l0 = 0.0f, l1 = 0.0f;

    for (int kb = 0; kb < nkv; kb++) {
        if (kb + 2 < nkv) {
            F_FILL((kb + 2) & 3, kb + 2);
            cp_commit();
            asm volatile("cp.async.wait_group 2;");
        } else if (kb + 1 < nkv) {
            asm volatile("cp.async.wait_group 1;");
        } else {
            asm volatile("cp.async.wait_group 0;");
        }
        __syncthreads();

        const uint32_t kbase = smb + OFF_KV0 + (kb & 3) * KVSTAGE;

        float sacc[8][4];
#pragma unroll
        for (int nf = 0; nf < 8; nf++)
#pragma unroll
            for (int e = 0; e < 4; e++) sacc[nf][e] = 0.0f;

#pragma unroll
        for (int kki = 0; kki < 4; kki++) {
            uint32_t ah[4];
            ldsm4(ah, qaddr0 + kki * 32);
#pragma unroll
            for (int kg = 0; kg < 4; kg++) {
                uint32_t bh[4];
                ldsm4(bh, kbase + krel + kg * 16 * FSTRB + kki * 32);
                mma16816(sacc[2 * kg],     ah, bh[0], bh[1]);
                mma16816(sacc[2 * kg + 1], ah, bh[2], bh[3]);
            }
        }

        if (kb >= 2 * qb) {
            const int qrow = qb * BQ + mrow + g;
            const int kc0  = kb * BKV + 2 * tig;
#pragma unroll
            for (int nf = 0; nf < 8; nf++) {
                int c = kc0 + nf * 8;
                if (c     > qrow)     sacc[nf][0] = -1e30f;
                if (c + 1 > qrow)     sacc[nf][1] = -1e30f;
                if (c     > qrow + 8) sacc[nf][2] = -1e30f;
                if (c + 1 > qrow + 8) sacc[nf][3] = -1e30f;
            }
        }

        float bm0 = -1e30f, bm1 = -1e30f;
#pragma unroll
        for (int nf = 0; nf < 8; nf++) {
            bm0 = fmaxf(bm0, fmaxf(sacc[nf][0], sacc[nf][1]));
            bm1 = fmaxf(bm1, fmaxf(sacc[nf][2], sacc[nf][3]));
        }
        bm0 = fmaxf(bm0, __shfl_xor_sync(0xffffffffu, bm0, 1));
        bm0 = fmaxf(bm0, __shfl_xor_sync(0xffffffffu, bm0, 2));
        bm1 = fmaxf(bm1, __shfl_xor_sync(0xffffffffu, bm1, 1));
        bm1 = fmaxf(bm1, __shfl_xor_sync(0xffffffffu, bm1, 2));

        const float mn0 = fmaxf(m0, bm0);
        const float mn1 = fmaxf(m1, bm1);
        const float a0 = ex2(m0 - mn0);
        const float a1 = ex2(m1 - mn1);
        m0 = mn0; m1 = mn1;

        uint32_t pfrag[16];
        float rs0 = 0.0f, rs1 = 0.0f;
#pragma unroll
        for (int nf = 0; nf < 8; nf++) {
            float fa, fb;
            pfrag[2 * nf] = h2exp2_pack(sacc[nf][0] - mn0, sacc[nf][1] - mn0, fa, fb);
            rs0 += fa + fb;
            pfrag[2 * nf + 1] = h2exp2_pack(sacc[nf][2] - mn1, sacc[nf][3] - mn1, fa, fb);
            rs1 += fa + fb;
        }
        rs0 += __shfl_xor_sync(0xffffffffu, rs0, 1);
        rs0 += __shfl_xor_sync(0xffffffffu, rs0, 2);
        rs1 += __shfl_xor_sync(0xffffffffu, rs1, 1);
        rs1 += __shfl_xor_sync(0xffffffffu, rs1, 2);
        l0 = l0 * a0 + rs0;
        l1 = l1 * a1 + rs1;

#pragma unroll
        for (int nf = 0; nf < 8; nf++) {
            oacc[nf][0] *= a0; oacc[nf][1] *= a0;
            oacc[nf][2] *= a1; oacc[nf][3] *= a1;
        }

#pragma unroll
        for (int kki = 0; kki < 4; kki++) {
            uint32_t ph[4];
            ph[0] = pfrag[4 * kki];
            ph[1] = pfrag[4 * kki + 1];
            ph[2] = pfrag[4 * kki + 2];
            ph[3] = pfrag[4 * kki + 3];
#pragma unroll
            for (int dg = 0; dg < 4; dg++) {
                uint32_t vh[4];
                ldsm4t(vh, kbase + VH_REL + vrel + kki * 16 * FSTRB + dg * 32);
                mma16816(oacc[2 * dg],     ph, vh[0], vh[1]);
                mma16816(oacc[2 * dg + 1], ph, vh[2], vh[3]);
            }
        }
    }
#undef F_FILL

    const float inv0 = 1.0f / l0;
    const float inv1 = 1.0f / l1;
    const int orow = qb * BQ + mrow + g;
#pragma unroll
    for (int nf = 0; nf < 8; nf++) {
        const int col = nf * 8 + 2 * tig;
        *(uint32_t*)(Oh + base + (size_t)orow * DMODEL + col) =
            pack_f16(oacc[nf][0] * inv0, oacc[nf][1] * inv0);
        *(uint32_t*)(Oh + base + (size_t)(orow + 8) * DMODEL + col) =
            pack_f16(oacc[nf][2] * inv1, oacc[nf][3] * inv1);
    }
}

// ===========================================================================
extern "C" void kernel_launch(void* const* d_in, const int* in_sizes, int n_in,
                              void* d_out, int out_size)
{
    (void)in_sizes; (void)n_in; (void)out_size;

    const float* X  = (const float*)d_in[0];
    const float* Wq = (const float*)d_in[2];
    const float* Wk = (const float*)d_in[3];
    const float* Wv = (const float*)d_in[4];
    const float* Wo = (const float*)d_in[5];
    float* out = (float*)d_out;

    __half *Xh, *Wqh, *Wkh, *Wvh, *Woh, *Qh, *Kh, *Vh, *AOh;
    cudaGetSymbolAddress((void**)&Xh,  g_Xh);
    cudaGetSymbolAddress((void**)&Wqh, g_Wqh);
    cudaGetSymbolAddress((void**)&Wkh, g_Wkh);
    cudaGetSymbolAddress((void**)&Wvh, g_Wvh);
    cudaGetSymbolAddress((void**)&Woh, g_Woh);
    cudaGetSymbolAddress((void**)&Qh,  g_Qh);
    cudaGetSymbolAddress((void**)&Kh,  g_Kh);
    cudaGetSymbolAddress((void**)&Vh,  g_Vh);
    cudaGetSymbolAddress((void**)&AOh, g_AOh);

    const int M = BATCH * SEQ;           // 4096
    const int NW4 = DMODEL * DMODEL / 4;

    dim3 gC((NW4 + 255) / 256, 8);       // X as 4 chunks + 4 weights
    conv_all<<<gC, 256>>>(X, Wq, Wk, Wv, Wo, Xh, Wqh, Wkh, Wvh, Woh, NW4);

    cudaFuncSetAttribute(gemm_qkv, cudaFuncAttributeMaxDynamicSharedMemorySize,
                         G2_SMEM);
    cudaFuncSetAttribute(gemm_out, cudaFuncAttributeMaxDynamicSharedMemorySize,
                         G2_SMEM);

    dim3 gQKV(DMODEL / 128, M / 128, 3);  // (8, 32, 3)
    gemm_qkv<<<gQKV, 256, G2_SMEM>>>(Xh, Wqh, Wkh, Wvh, Qh, Kh, Vh,
                                     M, DMODEL, DMODEL);

    cudaFuncSetAttribute(flash_mma, cudaFuncAttributeMaxDynamicSharedMemorySize,
                         FLASH_SMEM);
    dim3 gAttn(SEQ / BQ, NHEAD, BATCH);  // (16, 16, 2)
    flash_mma<<<gAttn, 256, FLASH_SMEM>>>(Qh, Kh, Vh, AOh);

    dim3 gProj(DMODEL / 128, M / 128);   // (8, 32)
    gemm_out<<<gProj, 256, G2_SMEM>>>(AOh, Woh, out, M, DMODEL, DMODEL);
}